// round 1
// baseline (speedup 1.0000x reference)
#include <cuda_runtime.h>

// Constants from the reference
#define N_UNITS 8
#define M_ATOMS 1024
#define NPTS (N_UNITS * M_ATOMS)      // 8192
#define N_PAIRS 28                    // 8*7/2 ordered unit pairs
#define LOG2E 1.4426950408889634f
#define ALPHA 1.0f
#define LAMBDA1 0.5f

// Scratch (allocation-free: __device__ globals)
// g_u: (2*log2e*x, 2*log2e*y, 2*log2e*z, h) ;  g_v: (x, y, z, h)
// arg2(pair) = u_i.x*v_j.x + u_i.y*v_j.y + u_i.z*v_j.z + (u_i.w + v_j.w)
//            = log2e * (1 - sq_i - sq_j + 2*dot)   ->  pen = exp2(arg2)
__device__ float4 g_u[NPTS];
__device__ float4 g_v[NPTS];

__device__ __forceinline__ float ex2_approx(float x) {
    float y;
    asm("ex2.approx.ftz.f32 %0, %1;" : "=f"(y) : "f"(x));
    return y;
}

__global__ void k_zero(float* __restrict__ out) {
    out[0] = 0.0f;
}

// Transform kernel: 8192 threads. Computes transformed points, stores u/v,
// accumulates L1 = sum(sq)/8 and (thread 0) L_com.
__global__ void k_transform(const float* __restrict__ pos,
                            const float* __restrict__ eul,
                            const float* __restrict__ coord,
                            float* __restrict__ out)
{
    int idx = blockIdx.x * blockDim.x + threadIdx.x;   // 0..8191
    int n = idx >> 10;
    int m = idx & (M_ATOMS - 1);

    float phi   = eul[3 * n + 0];
    float theta = eul[3 * n + 1];
    float psi   = eul[3 * n + 2];
    float sp, cp, st, ct, ss, cs;
    sincosf(phi,   &sp, &cp);
    sincosf(theta, &st, &ct);
    sincosf(psi,   &ss, &cs);

    // R = Rz(psi) * Ry(theta) * Rx(phi)
    float r00 = cs * ct;
    float r01 = cs * st * sp - ss * cp;
    float r02 = cs * st * cp + ss * sp;
    float r10 = ss * ct;
    float r11 = ss * st * sp + cs * cp;
    float r12 = ss * st * cp - cs * sp;
    float r20 = -st;
    float r21 = ct * sp;
    float r22 = ct * cp;

    float cx = coord[3 * m + 0];
    float cy = coord[3 * m + 1];
    float cz = coord[3 * m + 2];
    float px = pos[3 * n + 0];
    float py = pos[3 * n + 1];
    float pz = pos[3 * n + 2];

    float tx = fmaf(r00, cx, fmaf(r01, cy, fmaf(r02, cz, px)));
    float ty = fmaf(r10, cx, fmaf(r11, cy, fmaf(r12, cz, py)));
    float tz = fmaf(r20, cx, fmaf(r21, cy, fmaf(r22, cz, pz)));

    float sq = fmaf(tx, tx, fmaf(ty, ty, tz * tz));
    float h  = LOG2E * (0.5f - sq);

    g_v[idx] = make_float4(tx, ty, tz, h);
    g_u[idx] = make_float4(2.0f * LOG2E * tx,
                           2.0f * LOG2E * ty,
                           2.0f * LOG2E * tz, h);

    // Block reduction of sq for L1
    float t = sq;
    #pragma unroll
    for (int o = 16; o > 0; o >>= 1)
        t += __shfl_down_sync(0xFFFFFFFFu, t, o);

    __shared__ float ws[8];   // blockDim = 256 -> 8 warps
    int lane = threadIdx.x & 31;
    int wid  = threadIdx.x >> 5;
    if (lane == 0) ws[wid] = t;
    __syncthreads();
    if (threadIdx.x == 0) {
        float s = 0.0f;
        #pragma unroll
        for (int w = 0; w < 8; w++) s += ws[w];
        atomicAdd(out, s * (1.0f / (float)N_UNITS));   // L1 contribution
    }

    if (idx == 0) {
        // L_com = ALPHA * ||sum positions||^2
        float sx = 0.0f, sy = 0.0f, sz = 0.0f;
        #pragma unroll
        for (int k = 0; k < N_UNITS; k++) {
            sx += pos[3 * k + 0];
            sy += pos[3 * k + 1];
            sz += pos[3 * k + 2];
        }
        atomicAdd(out, ALPHA * (sx * sx + sy * sy + sz * sz));
    }
}

// Pair kernel: 28 unit-pairs, each 1024x1024 block of pairs.
// CTA = 128 threads; each thread owns 4 consecutive i-points (i-tile = 512),
// loops over a 32-wide j-tile. Grid = 28 * 2 * 32 = 1792 CTAs.
#define TPB 128
#define I_PER_THREAD 4
#define ITILE (TPB * I_PER_THREAD)   // 512
#define JTILE 32

__global__ void __launch_bounds__(TPB) k_pairs(float* __restrict__ out)
{
    int bid     = blockIdx.x;
    int pairIdx = bid >> 6;          // / (2 * 32)
    int rem     = bid & 63;
    int iTile   = rem >> 5;          // 0..1
    int jTile   = rem & 31;          // 0..31

    // pairIdx -> (a, b), a < b
    int p = pairIdx, a = 0, cnt = N_UNITS - 1;
    while (p >= cnt) { p -= cnt; ++a; --cnt; }
    int b = a + 1 + p;

    int ibase = a * M_ATOMS + iTile * ITILE + threadIdx.x * I_PER_THREAD;
    int jbase = b * M_ATOMS + jTile * JTILE;

    float4 u0 = g_u[ibase + 0];
    float4 u1 = g_u[ibase + 1];
    float4 u2 = g_u[ibase + 2];
    float4 u3 = g_u[ibase + 3];

    float acc0 = 0.0f, acc1 = 0.0f, acc2 = 0.0f, acc3 = 0.0f;

    #pragma unroll 8
    for (int j = 0; j < JTILE; j++) {
        float4 v = __ldg(&g_v[jbase + j]);
        float s0 = fmaf(u0.x, v.x, fmaf(u0.y, v.y, fmaf(u0.z, v.z, u0.w + v.w)));
        float s1 = fmaf(u1.x, v.x, fmaf(u1.y, v.y, fmaf(u1.z, v.z, u1.w + v.w)));
        float s2 = fmaf(u2.x, v.x, fmaf(u2.y, v.y, fmaf(u2.z, v.z, u2.w + v.w)));
        float s3 = fmaf(u3.x, v.x, fmaf(u3.y, v.y, fmaf(u3.z, v.z, u3.w + v.w)));
        acc0 += ex2_approx(s0);
        acc1 += ex2_approx(s1);
        acc2 += ex2_approx(s2);
        acc3 += ex2_approx(s3);
    }

    float t = (acc0 + acc1) + (acc2 + acc3);
    #pragma unroll
    for (int o = 16; o > 0; o >>= 1)
        t += __shfl_down_sync(0xFFFFFFFFu, t, o);

    __shared__ float ws[TPB / 32];
    int lane = threadIdx.x & 31;
    int wid  = threadIdx.x >> 5;
    if (lane == 0) ws[wid] = t;
    __syncthreads();
    if (threadIdx.x == 0) {
        float s = 0.0f;
        #pragma unroll
        for (int w = 0; w < TPB / 32; w++) s += ws[w];
        atomicAdd(out, LAMBDA1 * s);
    }
}

extern "C" void kernel_launch(void* const* d_in, const int* in_sizes, int n_in,
                              void* d_out, int out_size)
{
    const float* positions    = (const float*)d_in[0];
    const float* euler_angles = (const float*)d_in[1];
    const float* coordinates  = (const float*)d_in[2];
    float* out = (float*)d_out;

    (void)in_sizes; (void)n_in; (void)out_size;

    k_zero<<<1, 1>>>(out);
    k_transform<<<NPTS / 256, 256>>>(positions, euler_angles, coordinates, out);
    k_pairs<<<N_PAIRS * 2 * (M_ATOMS / JTILE), TPB>>>(out);
}

// round 3
// speedup vs baseline: 1.1157x; 1.1157x over previous
#include <cuda_runtime.h>

#define N_UNITS 8
#define M_ATOMS 1024
#define NPTS (N_UNITS * M_ATOMS)      // 8192
#define N_PAIRS 28
#define LOG2E 1.4426950408889634f
#define ALPHA 1.0f
#define LAMBDA1 0.5f

// ---------------- device scratch (allocation-free) ----------------
// g_u[idx] = (2*log2e*x, 2*log2e*y, 2*log2e*z, h) for each transformed point
// g_vp: transposed j-side layout, per unit, per j-pair jj:
//   [jj][0] = {x_{2jj}, x_{2jj+1}}  packed as 2 floats (8 bytes)
//   [jj][1] = {y,y} ; [jj][2] = {z,z} ; [jj][3] = {h,h}
// so one jj entry = 32 bytes, loadable as two 16B vectors.
__device__ float4 g_u[NPTS];
__device__ __align__(16) float g_vp[N_UNITS][M_ATOMS / 2][4][2];
__device__ float g_acc;          // zero-initialized; reset by last CTA each run
__device__ unsigned int g_count; // zero-initialized; reset by last CTA each run

// ---------------- helpers ----------------
__device__ __forceinline__ float ex2_approx(float x) {
    float y;
    asm("ex2.approx.ftz.f32 %0, %1;" : "=f"(y) : "f"(x));
    return y;
}
__device__ __forceinline__ unsigned long long pack2(float a, float b) {
    unsigned long long r;
    asm("mov.b64 %0, {%1, %2};" : "=l"(r) : "f"(a), "f"(b));
    return r;
}
__device__ __forceinline__ void unpack2(unsigned long long p, float& lo, float& hi) {
    asm("mov.b64 {%0, %1}, %2;" : "=f"(lo), "=f"(hi) : "l"(p));
}
__device__ __forceinline__ unsigned long long fma2(unsigned long long a,
                                                   unsigned long long b,
                                                   unsigned long long c) {
    unsigned long long d;
    asm("fma.rn.f32x2 %0, %1, %2, %3;" : "=l"(d) : "l"(a), "l"(b), "l"(c));
    return d;
}
__device__ __forceinline__ unsigned long long add2(unsigned long long a,
                                                   unsigned long long b) {
    unsigned long long d;
    asm("add.rn.f32x2 %0, %1, %2;" : "=l"(d) : "l"(a), "l"(b));
    return d;
}

// ---------------- kernel 1: prep ----------------
// grid = 32 blocks x 256 threads; block covers 256 consecutive points of ONE unit.
// Computes rotation matrix once per block (thread 0), transforms points,
// writes g_u (i-side) and g_vp (j-side transposed), accumulates L1 and L_com
// into g_acc via atomics.
__global__ void __launch_bounds__(256) k_prep(const float* __restrict__ pos,
                                              const float* __restrict__ eul,
                                              const float* __restrict__ coord)
{
    __shared__ float sR[12];  // r00..r22, px, py, pz
    int bid = blockIdx.x;
    int n = bid >> 2;                       // unit (4 blocks per unit)
    int m = ((bid & 3) << 8) + threadIdx.x; // atom index within unit

    if (threadIdx.x == 0) {
        float phi   = eul[3 * n + 0];
        float theta = eul[3 * n + 1];
        float psi   = eul[3 * n + 2];
        float sp, cp, st, ct, ss, cs;
        sincosf(phi,   &sp, &cp);
        sincosf(theta, &st, &ct);
        sincosf(psi,   &ss, &cs);
        sR[0] = cs * ct;
        sR[1] = cs * st * sp - ss * cp;
        sR[2] = cs * st * cp + ss * sp;
        sR[3] = ss * ct;
        sR[4] = ss * st * sp + cs * cp;
        sR[5] = ss * st * cp - cs * sp;
        sR[6] = -st;
        sR[7] = ct * sp;
        sR[8] = ct * cp;
        sR[9]  = pos[3 * n + 0];
        sR[10] = pos[3 * n + 1];
        sR[11] = pos[3 * n + 2];
    }
    __syncthreads();

    float cx = coord[3 * m + 0];
    float cy = coord[3 * m + 1];
    float cz = coord[3 * m + 2];

    float tx = fmaf(sR[0], cx, fmaf(sR[1], cy, fmaf(sR[2], cz, sR[9])));
    float ty = fmaf(sR[3], cx, fmaf(sR[4], cy, fmaf(sR[5], cz, sR[10])));
    float tz = fmaf(sR[6], cx, fmaf(sR[7], cy, fmaf(sR[8], cz, sR[11])));

    float sq = fmaf(tx, tx, fmaf(ty, ty, tz * tz));
    float h  = LOG2E * (0.5f - sq);

    int idx = n * M_ATOMS + m;
    g_u[idx] = make_float4(2.0f * LOG2E * tx,
                           2.0f * LOG2E * ty,
                           2.0f * LOG2E * tz, h);

    int jj = m >> 1, half = m & 1;
    g_vp[n][jj][0][half] = tx;
    g_vp[n][jj][1][half] = ty;
    g_vp[n][jj][2][half] = tz;
    g_vp[n][jj][3][half] = h;

    // L1 = sum(sq) / N_UNITS  (block reduction -> atomic)
    float t = sq;
    #pragma unroll
    for (int o = 16; o > 0; o >>= 1)
        t += __shfl_down_sync(0xFFFFFFFFu, t, o);
    __shared__ float ws[8];
    int lane = threadIdx.x & 31, wid = threadIdx.x >> 5;
    if (lane == 0) ws[wid] = t;
    __syncthreads();
    if (threadIdx.x == 0) {
        float s = 0.0f;
        #pragma unroll
        for (int w = 0; w < 8; w++) s += ws[w];
        atomicAdd(&g_acc, s * (1.0f / (float)N_UNITS));
    }

    if (bid == 0 && threadIdx.x == 32) {
        float sx = 0.0f, sy = 0.0f, sz = 0.0f;
        #pragma unroll
        for (int k = 0; k < N_UNITS; k++) {
            sx += pos[3 * k + 0];
            sy += pos[3 * k + 1];
            sz += pos[3 * k + 2];
        }
        atomicAdd(&g_acc, ALPHA * (sx * sx + sy * sy + sz * sz));
    }
}

// ---------------- kernel 2: pairs ----------------
// 28 unit pairs x (2 i-tiles of 512) x (32 j-tiles of 32) = 1792 CTAs, 128 thr.
// Each thread: 4 i-points x 32 j-points = 128 pairs, packed 2-wide over j.
#define TPB 128
#define I_PER_THREAD 4
#define ITILE (TPB * I_PER_THREAD)  // 512
#define JTILE 32
#define NJJ (JTILE / 2)             // 16 packed iterations
#define PAIR_CTAS (N_PAIRS * 2 * (M_ATOMS / JTILE))  // 1792

__global__ void __launch_bounds__(TPB) k_pairs(float* __restrict__ out)
{
    int bid     = blockIdx.x;
    int pairIdx = bid >> 6;
    int rem     = bid & 63;
    int iTile   = rem >> 5;
    int jTile   = rem & 31;

    int p = pairIdx, a = 0, cnt = N_UNITS - 1;
    while (p >= cnt) { p -= cnt; ++a; --cnt; }
    int b = a + 1 + p;

    int ibase = a * M_ATOMS + iTile * ITILE + threadIdx.x * I_PER_THREAD;
    int jj0   = jTile * NJJ;

    // i-side: load 4 points, pack each component 2-wide (duplicated)
    unsigned long long ux[I_PER_THREAD], uy[I_PER_THREAD],
                       uz[I_PER_THREAD], uw[I_PER_THREAD];
    #pragma unroll
    for (int k = 0; k < I_PER_THREAD; k++) {
        float4 u = __ldg(&g_u[ibase + k]);
        ux[k] = pack2(u.x, u.x);
        uy[k] = pack2(u.y, u.y);
        uz[k] = pack2(u.z, u.z);
        uw[k] = pack2(u.w, u.w);
    }

    float accA[I_PER_THREAD] = {0.f, 0.f, 0.f, 0.f};
    float accB[I_PER_THREAD] = {0.f, 0.f, 0.f, 0.f};

    const ulonglong2* __restrict__ vp =
        (const ulonglong2*)&g_vp[b][jj0][0][0];

    #pragma unroll
    for (int q = 0; q < NJJ; q++) {
        ulonglong2 P0 = vp[2 * q + 0];  // {xx, yy}
        ulonglong2 P1 = vp[2 * q + 1];  // {zz, ww}
        #pragma unroll
        for (int k = 0; k < I_PER_THREAD; k++) {
            unsigned long long s2 =
                fma2(ux[k], P0.x,
                fma2(uy[k], P0.y,
                fma2(uz[k], P1.x,
                add2(uw[k], P1.y))));
            float lo, hi;
            unpack2(s2, lo, hi);
            accA[k] += ex2_approx(lo);
            accB[k] += ex2_approx(hi);
        }
    }

    float t = ((accA[0] + accB[0]) + (accA[1] + accB[1])) +
              ((accA[2] + accB[2]) + (accA[3] + accB[3]));
    #pragma unroll
    for (int o = 16; o > 0; o >>= 1)
        t += __shfl_down_sync(0xFFFFFFFFu, t, o);

    __shared__ float ws[TPB / 32];
    int lane = threadIdx.x & 31, wid = threadIdx.x >> 5;
    if (lane == 0) ws[wid] = t;
    __syncthreads();

    if (threadIdx.x == 0) {
        float s = 0.0f;
        #pragma unroll
        for (int w = 0; w < TPB / 32; w++) s += ws[w];
        atomicAdd(&g_acc, LAMBDA1 * s);
        __threadfence();
        unsigned int nDone = atomicAdd(&g_count, 1u);
        if (nDone == PAIR_CTAS - 1) {
            // last CTA: publish result, reset state for next graph replay
            float total = atomicExch(&g_acc, 0.0f);
            out[0] = total;
            atomicExch(&g_count, 0u);
        }
    }
}

extern "C" void kernel_launch(void* const* d_in, const int* in_sizes, int n_in,
                              void* d_out, int out_size)
{
    const float* positions    = (const float*)d_in[0];
    const float* euler_angles = (const float*)d_in[1];
    const float* coordinates  = (const float*)d_in[2];
    float* out = (float*)d_out;
    (void)in_sizes; (void)n_in; (void)out_size;

    k_prep<<<NPTS / 256, 256>>>(positions, euler_angles, coordinates);
    k_pairs<<<PAIR_CTAS, TPB>>>(out);
}